// round 4
// baseline (speedup 1.0000x reference)
#include <cuda_runtime.h>
#include <cstdint>
#include <cstddef>

#define NN 50000
#define EE 400000
#define DD 512
#define GG 128
#define LL 4

// ---------------- scratch (static device allocations; no cudaMalloc) -------
__device__ float g_z[(size_t)NN * DD];   // layer input (BN output)
__device__ float g_h[(size_t)NN * DD];   // agg output / gemm2 output (pre-BN)
__device__ float g_t[(size_t)NN * DD];   // gemm1 output
__device__ int   g_deg[NN];
__device__ int   g_rowptr[NN + 1];
__device__ int   g_cursor[NN];
__device__ int   g_colidx[EE];
__device__ int   g_gc[GG];
__device__ int   g_gstart[GG + 1];
__device__ float g_invcnt[GG];
__device__ float g_sum[DD];
__device__ float g_sq[DD];
__device__ float g_mu[DD];
__device__ float g_rstd[DD];

// ---------------- CSR build -------------------------------------------------
__global__ void zero_csr_kernel() {
    int i = blockIdx.x * blockDim.x + threadIdx.x;
    int stride = gridDim.x * blockDim.x;
    for (int j = i; j < NN; j += stride) g_deg[j] = 0;
    if (i < GG) g_gc[i] = 0;
}

__global__ void edge_hist_kernel(const int* __restrict__ ei) {
    int e = blockIdx.x * blockDim.x + threadIdx.x;
    if (e < EE) atomicAdd(&g_deg[ei[EE + e]], 1);
}

__global__ void node_hist_kernel(const int* __restrict__ batch) {
    int i = blockIdx.x * blockDim.x + threadIdx.x;
    if (i < NN) atomicAdd(&g_gc[batch[i]], 1);
}

__global__ void scan_kernel() {
    __shared__ int sh[1024];
    __shared__ int carry_s;
    int tid = threadIdx.x;
    if (tid == 0) { carry_s = 0; g_rowptr[0] = 0; }
    __syncthreads();
    for (int base = 0; base < NN; base += 1024) {
        int i = base + tid;
        int v = (i < NN) ? g_deg[i] : 0;
        sh[tid] = v;
        __syncthreads();
        for (int off = 1; off < 1024; off <<= 1) {
            int t = (tid >= off) ? sh[tid - off] : 0;
            __syncthreads();
            sh[tid] += t;
            __syncthreads();
        }
        int inc = sh[tid];
        int c = carry_s;
        if (i < NN) {
            g_rowptr[i + 1] = c + inc;
            g_cursor[i]     = c + inc - v;
        }
        __syncthreads();
        if (tid == 0) carry_s = c + sh[1023];
        __syncthreads();
    }
}

__global__ void scatter_kernel(const int* __restrict__ ei) {
    int e = blockIdx.x * blockDim.x + threadIdx.x;
    if (e < EE) {
        int d = ei[EE + e];
        int p = atomicAdd(&g_cursor[d], 1);
        g_colidx[p] = ei[e];
    }
}

__global__ void gscan_kernel() {
    if (threadIdx.x == 0) {
        int acc = 0;
        for (int g = 0; g < GG; g++) {
            g_gstart[g] = acc;
            int c = g_gc[g];
            acc += c;
            g_invcnt[g] = 1.0f / (float)(c > 1 ? c : 1);
        }
        g_gstart[GG] = acc;
    }
}

// ---------------- GIN aggregation: h[n] = z[n] + sum_{src->n} z[src] --------
__global__ void agg_kernel(const float* __restrict__ xin) {
    const float* __restrict__ zin = xin ? xin : g_z;
    int n = blockIdx.x;
    int t = threadIdx.x;           // 128 threads, one float4 each
    const float4* Z = (const float4*)zin;
    float4 acc = Z[(size_t)n * 128 + t];
    int e = g_rowptr[n], end = g_rowptr[n + 1];
    for (; e + 4 <= end; e += 4) {
        int s0 = g_colidx[e], s1 = g_colidx[e + 1], s2 = g_colidx[e + 2], s3 = g_colidx[e + 3];
        float4 v0 = Z[(size_t)s0 * 128 + t];
        float4 v1 = Z[(size_t)s1 * 128 + t];
        float4 v2 = Z[(size_t)s2 * 128 + t];
        float4 v3 = Z[(size_t)s3 * 128 + t];
        acc.x += v0.x + v1.x + v2.x + v3.x;
        acc.y += v0.y + v1.y + v2.y + v3.y;
        acc.z += v0.z + v1.z + v2.z + v3.z;
        acc.w += v0.w + v1.w + v2.w + v3.w;
    }
    for (; e < end; e++) {
        float4 v = Z[(size_t)g_colidx[e] * 128 + t];
        acc.x += v.x; acc.y += v.y; acc.z += v.z; acc.w += v.w;
    }
    ((float4*)g_h)[(size_t)n * 128 + t] = acc;
}

// ------------- GEMM: C = relu(A @ W + bias), 3xTF32 tensor cores ------------
__device__ __forceinline__ uint32_t f2tf(float f) {
    uint32_t r;
    asm("cvt.rna.tf32.f32 %0, %1;" : "=r"(r) : "f"(f));
    return r;
}
// split f into tf32 hi + tf32 lo (lo = tf32(f - float(hi)))
__device__ __forceinline__ void f2tf2(float f, uint32_t& hi, uint32_t& lo) {
    hi = f2tf(f);
    lo = f2tf(f - __uint_as_float(hi));
}

__device__ __forceinline__ void mma_tf32(float* c, const uint32_t* a, const uint32_t* b) {
    asm volatile(
        "mma.sync.aligned.m16n8k8.row.col.f32.tf32.tf32.f32 "
        "{%0,%1,%2,%3}, {%4,%5,%6,%7}, {%8,%9}, {%0,%1,%2,%3};\n"
        : "+f"(c[0]), "+f"(c[1]), "+f"(c[2]), "+f"(c[3])
        : "r"(a[0]), "r"(a[1]), "r"(a[2]), "r"(a[3]), "r"(b[0]), "r"(b[1]));
}

#define SA_N (128 * 36)
#define SB_N (32 * 136)
#define GEMM_SMEM_BYTES ((2 * SA_N + 2 * SB_N) * 4)

// Block tile 128x128, K-tile 32, 256 threads (8 warps, 4x2), warp tile 32x64.
__global__ __launch_bounds__(256) void gemm_relu_kernel(
    int sel, const float* __restrict__ W, const float* __restrict__ bias)
{
    const float* __restrict__ A = sel ? g_t : g_h;
    float* __restrict__ C       = sel ? g_h : g_t;

    extern __shared__ uint32_t smem[];
    uint32_t* sa_hi = smem;                  // [row][k] pad 36
    uint32_t* sa_lo = sa_hi + SA_N;
    uint32_t* sb_hi = sa_lo + SA_N;          // [k][n] pad 136
    uint32_t* sb_lo = sb_hi + SB_N;

    int tid  = threadIdx.x;
    int lane = tid & 31;
    int warp = tid >> 5;
    int wm = warp >> 1;      // 0..3
    int wn = warp & 1;       // 0..1
    int m0 = blockIdx.x * 128;
    int n0 = blockIdx.y * 128;

    float acc[2][8][4];
#pragma unroll
    for (int mi = 0; mi < 2; mi++)
#pragma unroll
        for (int ni = 0; ni < 8; ni++)
#pragma unroll
            for (int j = 0; j < 4; j++) acc[mi][ni][j] = 0.f;

    float4 ra[4], rb[4];

    auto loadA = [&](int kt) {
        int k0 = kt * 32;
#pragma unroll
        for (int j = 0; j < 4; j++) {
            int row = j * 32 + (tid >> 3);
            int col = (tid & 7) * 4;
            int gr = m0 + row;
            if (gr < NN) ra[j] = *(const float4*)(A + (size_t)gr * DD + k0 + col);
            else         ra[j] = make_float4(0.f, 0.f, 0.f, 0.f);
        }
    };
    auto loadB = [&](int kt) {
        int k0 = kt * 32;
#pragma unroll
        for (int j = 0; j < 4; j++) {
            int row = j * 8 + (tid >> 5);
            int col = (tid & 31) * 4;
            rb[j] = *(const float4*)(W + (size_t)(k0 + row) * DD + n0 + col);
        }
    };
    auto stsA = [&]() {
#pragma unroll
        for (int j = 0; j < 4; j++) {
            int row = j * 32 + (tid >> 3);
            int col = (tid & 7) * 4;
            int idx = row * 36 + col;
            uint32_t h0, l0, h1, l1, h2, l2, h3, l3;
            f2tf2(ra[j].x, h0, l0); f2tf2(ra[j].y, h1, l1);
            f2tf2(ra[j].z, h2, l2); f2tf2(ra[j].w, h3, l3);
            sa_hi[idx] = h0; sa_hi[idx + 1] = h1; sa_hi[idx + 2] = h2; sa_hi[idx + 3] = h3;
            sa_lo[idx] = l0; sa_lo[idx + 1] = l1; sa_lo[idx + 2] = l2; sa_lo[idx + 3] = l3;
        }
    };
    auto stsB = [&]() {
#pragma unroll
        for (int j = 0; j < 4; j++) {
            int row = j * 8 + (tid >> 5);
            int col = (tid & 31) * 4;
            int idx = row * 136 + col;
            uint32_t h0, l0, h1, l1, h2, l2, h3, l3;
            f2tf2(rb[j].x, h0, l0); f2tf2(rb[j].y, h1, l1);
            f2tf2(rb[j].z, h2, l2); f2tf2(rb[j].w, h3, l3);
            sb_hi[idx] = h0; sb_hi[idx + 1] = h1; sb_hi[idx + 2] = h2; sb_hi[idx + 3] = h3;
            sb_lo[idx] = l0; sb_lo[idx + 1] = l1; sb_lo[idx + 2] = l2; sb_lo[idx + 3] = l3;
        }
    };

    loadA(0); loadB(0);
    stsA(); stsB();
    __syncthreads();

    for (int kt = 0; kt < 16; kt++) {
        bool more = (kt + 1) < 16;
        if (more) { loadA(kt + 1); loadB(kt + 1); }

#pragma unroll
        for (int kk = 0; kk < 4; kk++) {
            uint32_t afh[2][4], afl[2][4], bfh[8][2], bfl[8][2];
            int ar = wm * 32 + (lane >> 2);
            int ac = kk * 8 + (lane & 3);
#pragma unroll
            for (int mi = 0; mi < 2; mi++) {
                int r0 = ar + mi * 16;
                int i00 = r0 * 36 + ac, i10 = (r0 + 8) * 36 + ac;
                afh[mi][0] = sa_hi[i00]; afh[mi][1] = sa_hi[i10];
                afh[mi][2] = sa_hi[i00 + 4]; afh[mi][3] = sa_hi[i10 + 4];
                afl[mi][0] = sa_lo[i00]; afl[mi][1] = sa_lo[i10];
                afl[mi][2] = sa_lo[i00 + 4]; afl[mi][3] = sa_lo[i10 + 4];
            }
            int bk = kk * 8 + (lane & 3);
            int bc = wn * 64 + (lane >> 2);
#pragma unroll
            for (int ni = 0; ni < 8; ni++) {
                int i0 = bk * 136 + bc + ni * 8;
                int i1 = (bk + 4) * 136 + bc + ni * 8;
                bfh[ni][0] = sb_hi[i0]; bfh[ni][1] = sb_hi[i1];
                bfl[ni][0] = sb_lo[i0]; bfl[ni][1] = sb_lo[i1];
            }
#pragma unroll
            for (int mi = 0; mi < 2; mi++)
#pragma unroll
                for (int ni = 0; ni < 8; ni++) {
                    mma_tf32(acc[mi][ni], afl[mi], bfh[ni]);   // a_lo * b_hi
                    mma_tf32(acc[mi][ni], afh[mi], bfl[ni]);   // a_hi * b_lo
                    mma_tf32(acc[mi][ni], afh[mi], bfh[ni]);   // a_hi * b_hi
                }
        }

        __syncthreads();
        if (more) { stsA(); stsB(); __syncthreads(); }
    }

    // epilogue: relu(acc + bias), float2 stores
    int rbase = m0 + wm * 32 + (lane >> 2);
    int cbase = n0 + wn * 64 + (lane & 3) * 2;
#pragma unroll
    for (int mi = 0; mi < 2; mi++) {
#pragma unroll
        for (int ni = 0; ni < 8; ni++) {
            int c = cbase + ni * 8;
            float b0 = __ldg(&bias[c]);
            float b1 = __ldg(&bias[c + 1]);
            int r = rbase + mi * 16;
            if (r < NN) {
                float2 v;
                v.x = fmaxf(acc[mi][ni][0] + b0, 0.f);
                v.y = fmaxf(acc[mi][ni][1] + b1, 0.f);
                *(float2*)(C + (size_t)r * DD + c) = v;
            }
            r += 8;
            if (r < NN) {
                float2 v;
                v.x = fmaxf(acc[mi][ni][2] + b0, 0.f);
                v.y = fmaxf(acc[mi][ni][3] + b1, 0.f);
                *(float2*)(C + (size_t)r * DD + c) = v;
            }
        }
    }
}

// ---------------- BatchNorm stats + normalize + pool ------------------------
__global__ void zero_stats_kernel() {
    int c = threadIdx.x;
    if (c < DD) { g_sum[c] = 0.f; g_sq[c] = 0.f; }
}

__global__ void bn_stats_kernel() {   // grid (4, S), block 128
    int col = blockIdx.x * 128 + threadIdx.x;
    float s = 0.f, q = 0.f;
    for (int r = blockIdx.y; r < NN; r += gridDim.y) {
        float v = g_h[(size_t)r * DD + col];
        s += v;
        q += v * v;
    }
    atomicAdd(&g_sum[col], s);
    atomicAdd(&g_sq[col], q);
}

__global__ void bn_finalize_kernel() {
    int c = threadIdx.x;
    if (c < DD) {
        float mu  = g_sum[c] * (1.0f / NN);
        float var = g_sq[c] * (1.0f / NN) - mu * mu;
        g_mu[c]   = mu;
        g_rstd[c] = rsqrtf(fmaxf(var, 0.f) + 1e-5f);
    }
}

// normalize g_h -> g_z (next layer input) and mean-pool per graph -> out
__global__ void bn_pool_kernel(float* __restrict__ out, int layer,
                               const float* __restrict__ gamma,
                               const float* __restrict__ beta)
{
    int g   = blockIdx.x;
    int col = blockIdx.y * 128 + threadIdx.x;
    int s = g_gstart[g], e = g_gstart[g + 1];
    float a = g_rstd[col] * __ldg(&gamma[col]);
    float b = __ldg(&beta[col]) - g_mu[col] * a;
    float acc = 0.f;
    for (int r = s; r < e; r++) {
        float v  = g_h[(size_t)r * DD + col];
        float vn = v * a + b;
        g_z[(size_t)r * DD + col] = vn;
        acc += vn;
    }
    out[g * (LL * DD) + layer * DD + col] = acc * g_invcnt[g];
}

// ---------------- launcher --------------------------------------------------
extern "C" void kernel_launch(void* const* d_in, const int* in_sizes, int n_in,
                              void* d_out, int out_size)
{
    const float* x     = (const float*)d_in[0];
    const float* W1    = (const float*)d_in[1];
    const float* b1    = (const float*)d_in[2];
    const float* W2    = (const float*)d_in[3];
    const float* b2    = (const float*)d_in[4];
    const float* gamma = (const float*)d_in[5];
    const float* beta  = (const float*)d_in[6];
    const int*   ei    = (const int*)d_in[7];     // int32 (JAX x64 disabled)
    const int*   batch = (const int*)d_in[8];     // int32
    float* out = (float*)d_out;

    static int smem_set = 0;
    if (!smem_set) {
        cudaFuncSetAttribute(gemm_relu_kernel,
                             cudaFuncAttributeMaxDynamicSharedMemorySize,
                             GEMM_SMEM_BYTES);
        smem_set = 1;
    }

    zero_csr_kernel<<<196, 256>>>();
    edge_hist_kernel<<<(EE + 255) / 256, 256>>>(ei);
    node_hist_kernel<<<(NN + 255) / 256, 256>>>(batch);
    scan_kernel<<<1, 1024>>>();
    scatter_kernel<<<(EE + 255) / 256, 256>>>(ei);
    gscan_kernel<<<1, 32>>>();

    dim3 ggrid((NN + 127) / 128, 4);
    for (int i = 0; i < LL; i++) {
        agg_kernel<<<NN, 128>>>(i == 0 ? x : nullptr);
        gemm_relu_kernel<<<ggrid, 256, GEMM_SMEM_BYTES>>>(0, W1 + (size_t)i * DD * DD, b1 + i * DD);
        gemm_relu_kernel<<<ggrid, 256, GEMM_SMEM_BYTES>>>(1, W2 + (size_t)i * DD * DD, b2 + i * DD);
        zero_stats_kernel<<<1, 512>>>();
        bn_stats_kernel<<<dim3(4, 256), 128>>>();
        bn_finalize_kernel<<<1, 512>>>();
        bn_pool_kernel<<<dim3(GG, 4), 128>>>(out, i, gamma, beta);
    }
}

// round 5
// speedup vs baseline: 1.0770x; 1.0770x over previous
#include <cuda_runtime.h>
#include <cuda_bf16.h>
#include <cstdint>
#include <cstddef>

#define NN 50000
#define EE 400000
#define DD 512
#define GG 128
#define LL 4
#define NSCAN_BLK 49   // ceil(50000/1024)

// ---------------- scratch (static device allocations; no cudaMalloc) -------
__device__ float g_z[(size_t)NN * DD];   // layer input (BN output)
__device__ float g_h[(size_t)NN * DD];   // agg output / gemm2 output (pre-BN)
__device__ float g_t[(size_t)NN * DD];   // gemm1 output
__device__ int   g_deg[NN];
__device__ int   g_rowptr[NN + 1];
__device__ int   g_cursor[NN];
__device__ int   g_colidx[EE];
__device__ int   g_bsum[NSCAN_BLK];
__device__ int   g_gc[GG];
__device__ int   g_gstart[GG + 1];
__device__ float g_invcnt[GG];
__device__ float g_sum[DD];
__device__ float g_sq[DD];
__device__ float g_mu[DD];
__device__ float g_rstd[DD];

// ---------------- CSR build -------------------------------------------------
__global__ void zero_csr_kernel() {
    int i = blockIdx.x * blockDim.x + threadIdx.x;
    int stride = gridDim.x * blockDim.x;
    for (int j = i; j < NN; j += stride) g_deg[j] = 0;
    if (i < GG) g_gc[i] = 0;
}

__global__ void edge_hist_kernel(const int* __restrict__ ei) {
    int e = blockIdx.x * blockDim.x + threadIdx.x;
    if (e < EE) atomicAdd(&g_deg[ei[EE + e]], 1);
}

__global__ void node_hist_kernel(const int* __restrict__ batch) {
    int i = blockIdx.x * blockDim.x + threadIdx.x;
    if (i < NN) atomicAdd(&g_gc[batch[i]], 1);
}

// pass 1: per-block inclusive scan of deg -> rowptr[i+1] (local), block sums
__global__ void scan1_kernel() {
    __shared__ int swarp[32];
    int tid = threadIdx.x;
    int i = blockIdx.x * 1024 + tid;
    int lane = tid & 31, w = tid >> 5;
    int v = (i < NN) ? g_deg[i] : 0;
    int x = v;
#pragma unroll
    for (int o = 1; o < 32; o <<= 1) {
        int y = __shfl_up_sync(0xffffffffu, x, o);
        if (lane >= o) x += y;
    }
    if (lane == 31) swarp[w] = x;
    __syncthreads();
    if (w == 0) {
        int s = swarp[lane];
#pragma unroll
        for (int o = 1; o < 32; o <<= 1) {
            int y = __shfl_up_sync(0xffffffffu, s, o);
            if (lane >= o) s += y;
        }
        swarp[lane] = s;
    }
    __syncthreads();
    int incl = x + (w > 0 ? swarp[w - 1] : 0);
    if (i < NN) g_rowptr[i + 1] = incl;
    if (tid == 1023) g_bsum[blockIdx.x] = incl;
}

// pass 2: exclusive scan of 49 block sums (trivial, single thread)
__global__ void scan2_kernel() {
    if (threadIdx.x == 0) {
        int acc = 0;
        for (int b = 0; b < NSCAN_BLK; b++) {
            int v = g_bsum[b];
            g_bsum[b] = acc;
            acc += v;
        }
    }
}

// pass 3: add block offsets, produce final rowptr + cursor
__global__ void scan3_kernel() {
    int i = blockIdx.x * 1024 + threadIdx.x;
    if (i < NN) {
        int val = g_rowptr[i + 1] + g_bsum[blockIdx.x];
        g_rowptr[i + 1] = val;
        g_cursor[i] = val - g_deg[i];
        if (i == 0) g_rowptr[0] = 0;
    }
}

__global__ void scatter_kernel(const int* __restrict__ ei) {
    int e = blockIdx.x * blockDim.x + threadIdx.x;
    if (e < EE) {
        int d = ei[EE + e];
        int p = atomicAdd(&g_cursor[d], 1);
        g_colidx[p] = ei[e];
    }
}

__global__ void gscan_kernel() {
    if (threadIdx.x == 0) {
        int acc = 0;
        for (int g = 0; g < GG; g++) {
            g_gstart[g] = acc;
            int c = g_gc[g];
            acc += c;
            g_invcnt[g] = 1.0f / (float)(c > 1 ? c : 1);
        }
        g_gstart[GG] = acc;
    }
}

// ---------------- GIN aggregation: h[n] = z[n] + sum_{src->n} z[src] --------
__global__ void agg_kernel(const float* __restrict__ xin) {
    const float* __restrict__ zin = xin ? xin : g_z;
    int n = blockIdx.x;
    int t = threadIdx.x;           // 128 threads, one float4 each
    const float4* Z = (const float4*)zin;
    float4 acc = Z[(size_t)n * 128 + t];
    int e = g_rowptr[n], end = g_rowptr[n + 1];
    for (; e + 4 <= end; e += 4) {
        int s0 = g_colidx[e], s1 = g_colidx[e + 1], s2 = g_colidx[e + 2], s3 = g_colidx[e + 3];
        float4 v0 = Z[(size_t)s0 * 128 + t];
        float4 v1 = Z[(size_t)s1 * 128 + t];
        float4 v2 = Z[(size_t)s2 * 128 + t];
        float4 v3 = Z[(size_t)s3 * 128 + t];
        acc.x += v0.x + v1.x + v2.x + v3.x;
        acc.y += v0.y + v1.y + v2.y + v3.y;
        acc.z += v0.z + v1.z + v2.z + v3.z;
        acc.w += v0.w + v1.w + v2.w + v3.w;
    }
    for (; e < end; e++) {
        float4 v = Z[(size_t)g_colidx[e] * 128 + t];
        acc.x += v.x; acc.y += v.y; acc.z += v.z; acc.w += v.w;
    }
    ((float4*)g_h)[(size_t)n * 128 + t] = acc;
}

// ------------- GEMM: C = relu(A @ W + bias), 3xBF16 tensor cores ------------
__device__ __forceinline__ void split2(float x, float y, uint32_t& hi, uint32_t& lo) {
    __nv_bfloat162 h = __floats2bfloat162_rn(x, y);        // .x = x (low 16 bits)
    float hx = __bfloat162float(h.x);
    float hy = __bfloat162float(h.y);
    __nv_bfloat162 l = __floats2bfloat162_rn(x - hx, y - hy);
    hi = *(uint32_t*)&h;
    lo = *(uint32_t*)&l;
}

__device__ __forceinline__ void mma_bf16(float* c, const uint32_t* a, const uint32_t* b) {
    asm volatile(
        "mma.sync.aligned.m16n8k16.row.col.f32.bf16.bf16.f32 "
        "{%0,%1,%2,%3}, {%4,%5,%6,%7}, {%8,%9}, {%0,%1,%2,%3};\n"
        : "+f"(c[0]), "+f"(c[1]), "+f"(c[2]), "+f"(c[3])
        : "r"(a[0]), "r"(a[1]), "r"(a[2]), "r"(a[3]), "r"(b[0]), "r"(b[1]));
}

#define SA_STRIDE 20    // uint32 per A row (16 k-pairs + pad) -> conflict-free frags
#define SB_STRIDE 132   // uint32 per B k-pair row (128 n + pad)

// Block tile 128x128, K-tile 32 (2 k16 steps), 256 threads (8 warps 4x2),
// warp tile 32x64. Operands staged in smem as packed bf16x2 hi/lo pairs.
__global__ __launch_bounds__(256) void gemm_relu_kernel(
    int sel, const float* __restrict__ W, const float* __restrict__ bias)
{
    const float* __restrict__ A = sel ? g_t : g_h;
    float* __restrict__ C       = sel ? g_h : g_t;

    __shared__ uint32_t sa_hi[128 * SA_STRIDE];
    __shared__ uint32_t sa_lo[128 * SA_STRIDE];
    __shared__ uint32_t sb_hi[16 * SB_STRIDE];
    __shared__ uint32_t sb_lo[16 * SB_STRIDE];

    int tid  = threadIdx.x;
    int lane = tid & 31;
    int warp = tid >> 5;
    int wm = warp >> 1;      // 0..3
    int wn = warp & 1;       // 0..1
    int m0 = blockIdx.x * 128;
    int n0 = blockIdx.y * 128;

    float acc[2][8][4];
#pragma unroll
    for (int mi = 0; mi < 2; mi++)
#pragma unroll
        for (int ni = 0; ni < 8; ni++)
#pragma unroll
            for (int j = 0; j < 4; j++) acc[mi][ni][j] = 0.f;

    float4 ra[4];
    float4 rb[4];

    auto loadA = [&](int kt) {
        int k0 = kt * 32;
#pragma unroll
        for (int j = 0; j < 4; j++) {
            int row = j * 32 + (tid >> 3);
            int col = (tid & 7) * 4;
            int gr = m0 + row;
            if (gr < NN) ra[j] = *(const float4*)(A + (size_t)gr * DD + k0 + col);
            else         ra[j] = make_float4(0.f, 0.f, 0.f, 0.f);
        }
    };
    auto loadB = [&](int kt) {
        int k0 = kt * 32;
        int kp = tid & 15;
        int nb = (tid >> 4) * 8;
        const float* p0 = W + (size_t)(k0 + 2 * kp) * DD + n0 + nb;
        const float* p1 = p0 + DD;
        rb[0] = *(const float4*)(p0);
        rb[1] = *(const float4*)(p0 + 4);
        rb[2] = *(const float4*)(p1);
        rb[3] = *(const float4*)(p1 + 4);
    };
    auto stsA = [&]() {
#pragma unroll
        for (int j = 0; j < 4; j++) {
            int row = j * 32 + (tid >> 3);
            int idx = row * SA_STRIDE + (tid & 7) * 2;
            uint32_t h0, l0, h1, l1;
            split2(ra[j].x, ra[j].y, h0, l0);
            split2(ra[j].z, ra[j].w, h1, l1);
            sa_hi[idx] = h0; sa_hi[idx + 1] = h1;
            sa_lo[idx] = l0; sa_lo[idx + 1] = l1;
        }
    };
    auto stsB = [&]() {
        int kp = tid & 15;
        int nb = (tid >> 4) * 8;
        int idx = kp * SB_STRIDE + nb;
#pragma unroll
        for (int i = 0; i < 4; i++) {
            float w0a = ((const float*)&rb[0])[i];   // row 2kp,   n nb+i
            float w1a = ((const float*)&rb[2])[i];   // row 2kp+1, n nb+i
            float w0b = ((const float*)&rb[1])[i];   // row 2kp,   n nb+4+i
            float w1b = ((const float*)&rb[3])[i];   // row 2kp+1, n nb+4+i
            uint32_t h, l;
            split2(w0a, w1a, h, l);
            sb_hi[idx + i] = h; sb_lo[idx + i] = l;
            split2(w0b, w1b, h, l);
            sb_hi[idx + 4 + i] = h; sb_lo[idx + 4 + i] = l;
        }
    };

    loadA(0); loadB(0);
    stsA(); stsB();
    __syncthreads();

    for (int kt = 0; kt < 16; kt++) {
        bool more = (kt + 1) < 16;
        if (more) { loadA(kt + 1); loadB(kt + 1); }

#pragma unroll
        for (int kk = 0; kk < 2; kk++) {
            uint32_t afh[2][4], afl[2][4], bfh[8][2], bfl[8][2];
            int ar = wm * 32 + (lane >> 2);
            int ac = kk * 8 + (lane & 3);
#pragma unroll
            for (int mi = 0; mi < 2; mi++) {
                int r0 = ar + mi * 16;
                int i00 = r0 * SA_STRIDE + ac;
                int i10 = (r0 + 8) * SA_STRIDE + ac;
                afh[mi][0] = sa_hi[i00];     afh[mi][1] = sa_hi[i10];
                afh[mi][2] = sa_hi[i00 + 4]; afh[mi][3] = sa_hi[i10 + 4];
                afl[mi][0] = sa_lo[i00];     afl[mi][1] = sa_lo[i10];
                afl[mi][2] = sa_lo[i00 + 4]; afl[mi][3] = sa_lo[i10 + 4];
            }
            int bk = kk * 8 + (lane & 3);
            int bc = wn * 64 + (lane >> 2);
#pragma unroll
            for (int ni = 0; ni < 8; ni++) {
                int i0 = bk * SB_STRIDE + bc + ni * 8;
                int i1 = (bk + 4) * SB_STRIDE + bc + ni * 8;
                bfh[ni][0] = sb_hi[i0]; bfh[ni][1] = sb_hi[i1];
                bfl[ni][0] = sb_lo[i0]; bfl[ni][1] = sb_lo[i1];
            }
#pragma unroll
            for (int mi = 0; mi < 2; mi++)
#pragma unroll
                for (int ni = 0; ni < 8; ni++) {
                    mma_bf16(acc[mi][ni], afl[mi], bfh[ni]);   // a_lo * b_hi
                    mma_bf16(acc[mi][ni], afh[mi], bfl[ni]);   // a_hi * b_lo
                    mma_bf16(acc[mi][ni], afh[mi], bfh[ni]);   // a_hi * b_hi
                }
        }

        __syncthreads();
        if (more) { stsA(); stsB(); __syncthreads(); }
    }

    int rbase = m0 + wm * 32 + (lane >> 2);
    int cbase = n0 + wn * 64 + (lane & 3) * 2;
#pragma unroll
    for (int mi = 0; mi < 2; mi++) {
#pragma unroll
        for (int ni = 0; ni < 8; ni++) {
            int c = cbase + ni * 8;
            float b0 = __ldg(&bias[c]);
            float b1 = __ldg(&bias[c + 1]);
            int r = rbase + mi * 16;
            if (r < NN) {
                float2 v;
                v.x = fmaxf(acc[mi][ni][0] + b0, 0.f);
                v.y = fmaxf(acc[mi][ni][1] + b1, 0.f);
                *(float2*)(C + (size_t)r * DD + c) = v;
            }
            r += 8;
            if (r < NN) {
                float2 v;
                v.x = fmaxf(acc[mi][ni][2] + b0, 0.f);
                v.y = fmaxf(acc[mi][ni][3] + b1, 0.f);
                *(float2*)(C + (size_t)r * DD + c) = v;
            }
        }
    }
}

// ---------------- BatchNorm stats + normalize + pool ------------------------
__global__ void zero_stats_kernel() {
    int c = threadIdx.x;
    if (c < DD) { g_sum[c] = 0.f; g_sq[c] = 0.f; }
}

__global__ void bn_stats_kernel() {   // grid (4, 256), block 128
    int col = blockIdx.x * 128 + threadIdx.x;
    float s = 0.f, q = 0.f;
    for (int r = blockIdx.y; r < NN; r += gridDim.y) {
        float v = g_h[(size_t)r * DD + col];
        s += v;
        q += v * v;
    }
    atomicAdd(&g_sum[col], s);
    atomicAdd(&g_sq[col], q);
}

__global__ void bn_finalize_kernel() {
    int c = threadIdx.x;
    if (c < DD) {
        float mu  = g_sum[c] * (1.0f / NN);
        float var = g_sq[c] * (1.0f / NN) - mu * mu;
        g_mu[c]   = mu;
        g_rstd[c] = rsqrtf(fmaxf(var, 0.f) + 1e-5f);
    }
}

__global__ void bn_pool_kernel(float* __restrict__ out, int layer,
                               const float* __restrict__ gamma,
                               const float* __restrict__ beta)
{
    int g   = blockIdx.x;
    int col = blockIdx.y * 128 + threadIdx.x;
    int s = g_gstart[g], e = g_gstart[g + 1];
    float a = g_rstd[col] * __ldg(&gamma[col]);
    float b = __ldg(&beta[col]) - g_mu[col] * a;
    float acc = 0.f;
    for (int r = s; r < e; r++) {
        float v  = g_h[(size_t)r * DD + col];
        float vn = v * a + b;
        g_z[(size_t)r * DD + col] = vn;
        acc += vn;
    }
    out[g * (LL * DD) + layer * DD + col] = acc * g_invcnt[g];
}

// ---------------- launcher --------------------------------------------------
extern "C" void kernel_launch(void* const* d_in, const int* in_sizes, int n_in,
                              void* d_out, int out_size)
{
    const float* x     = (const float*)d_in[0];
    const float* W1    = (const float*)d_in[1];
    const float* b1    = (const float*)d_in[2];
    const float* W2    = (const float*)d_in[3];
    const float* b2    = (const float*)d_in[4];
    const float* gamma = (const float*)d_in[5];
    const float* beta  = (const float*)d_in[6];
    const int*   ei    = (const int*)d_in[7];     // int32 (JAX x64 disabled)
    const int*   batch = (const int*)d_in[8];     // int32
    float* out = (float*)d_out;

    zero_csr_kernel<<<196, 256>>>();
    edge_hist_kernel<<<(EE + 255) / 256, 256>>>(ei);
    node_hist_kernel<<<(NN + 255) / 256, 256>>>(batch);
    scan1_kernel<<<NSCAN_BLK, 1024>>>();
    scan2_kernel<<<1, 32>>>();
    scan3_kernel<<<NSCAN_BLK, 1024>>>();
    scatter_kernel<<<(EE + 255) / 256, 256>>>(ei);
    gscan_kernel<<<1, 32>>>();

    dim3 ggrid((NN + 127) / 128, 4);
    for (int i = 0; i < LL; i++) {
        agg_kernel<<<NN, 128>>>(i == 0 ? x : nullptr);
        gemm_relu_kernel<<<ggrid, 256>>>(0, W1 + (size_t)i * DD * DD, b1 + i * DD);
        gemm_relu_kernel<<<ggrid, 256>>>(1, W2 + (size_t)i * DD * DD, b2 + i * DD);
        zero_stats_kernel<<<1, 512>>>();
        bn_stats_kernel<<<dim3(4, 256), 128>>>();
        bn_finalize_kernel<<<1, 512>>>();
        bn_pool_kernel<<<dim3(GG, 4), 128>>>(out, i, gamma, beta);
    }
}

// round 6
// speedup vs baseline: 1.5084x; 1.4005x over previous
#include <cuda_runtime.h>
#include <cuda_bf16.h>
#include <cstdint>
#include <cstddef>

#define NN 50000
#define NP 50048           // padded rows (multiple of 128)
#define EE 400000
#define DD 512
#define GG 128
#define LL 4
#define NSCAN_BLK 49       // ceil(50000/1024)

// ---------------- scratch (static device allocations; no cudaMalloc) -------
__device__ float g_z[(size_t)NN * DD];            // layer input (BN output), fp32
__device__ float g_h[(size_t)NN * DD];            // gemm2 output (pre-BN), fp32
__device__ __nv_bfloat16 g_ahi[(size_t)NP * DD];  // agg output, split hi
__device__ __nv_bfloat16 g_alo[(size_t)NP * DD];  // agg output, split lo
__device__ __nv_bfloat16 g_thi[(size_t)NP * DD];  // gemm1 output, split hi
__device__ __nv_bfloat16 g_tlo[(size_t)NP * DD];  // gemm1 output, split lo
__device__ __nv_bfloat16 g_whi[(size_t)8 * DD * DD];  // W^T split hi, [mat][n][k]
__device__ __nv_bfloat16 g_wlo[(size_t)8 * DD * DD];  // W^T split lo
__device__ int   g_deg[NN];
__device__ int   g_rowptr[NN + 1];
__device__ int   g_cursor[NN];
__device__ int   g_colidx[EE];
__device__ int   g_bsum[NSCAN_BLK];
__device__ int   g_gc[GG];
__device__ int   g_gstart[GG + 1];
__device__ float g_invcnt[GG];
__device__ float g_sum[DD];
__device__ float g_sq[DD];
__device__ float g_mu[DD];
__device__ float g_rstd[DD];

// ---------------- helpers ---------------------------------------------------
__device__ __forceinline__ void split2(float x, float y, uint32_t& hi, uint32_t& lo) {
    __nv_bfloat162 h = __floats2bfloat162_rn(x, y);   // .x in low 16 bits
    float hx = __bfloat162float(h.x);
    float hy = __bfloat162float(h.y);
    __nv_bfloat162 l = __floats2bfloat162_rn(x - hx, y - hy);
    hi = *(uint32_t*)&h;
    lo = *(uint32_t*)&l;
}

__device__ __forceinline__ void mma_bf16(float* c, const uint32_t* a, const uint32_t* b) {
    asm volatile(
        "mma.sync.aligned.m16n8k16.row.col.f32.bf16.bf16.f32 "
        "{%0,%1,%2,%3}, {%4,%5,%6,%7}, {%8,%9}, {%0,%1,%2,%3};\n"
        : "+f"(c[0]), "+f"(c[1]), "+f"(c[2]), "+f"(c[3])
        : "r"(a[0]), "r"(a[1]), "r"(a[2]), "r"(a[3]), "r"(b[0]), "r"(b[1]));
}

__device__ __forceinline__ void cp_async16(uint32_t saddr, const void* gaddr) {
    asm volatile("cp.async.cg.shared.global [%0], [%1], 16;\n"
                 :: "r"(saddr), "l"(gaddr));
}

// ---------------- CSR build -------------------------------------------------
__global__ void zero_csr_kernel() {
    int i = blockIdx.x * blockDim.x + threadIdx.x;
    int stride = gridDim.x * blockDim.x;
    for (int j = i; j < NN; j += stride) g_deg[j] = 0;
    if (i < GG) g_gc[i] = 0;
}

__global__ void edge_hist_kernel(const int* __restrict__ ei) {
    int e = blockIdx.x * blockDim.x + threadIdx.x;
    if (e < EE) atomicAdd(&g_deg[ei[EE + e]], 1);
}

__global__ void node_hist_kernel(const int* __restrict__ batch) {
    int i = blockIdx.x * blockDim.x + threadIdx.x;
    if (i < NN) atomicAdd(&g_gc[batch[i]], 1);
}

__global__ void scan1_kernel() {
    __shared__ int swarp[32];
    int tid = threadIdx.x;
    int i = blockIdx.x * 1024 + tid;
    int lane = tid & 31, w = tid >> 5;
    int v = (i < NN) ? g_deg[i] : 0;
    int x = v;
#pragma unroll
    for (int o = 1; o < 32; o <<= 1) {
        int y = __shfl_up_sync(0xffffffffu, x, o);
        if (lane >= o) x += y;
    }
    if (lane == 31) swarp[w] = x;
    __syncthreads();
    if (w == 0) {
        int s = swarp[lane];
#pragma unroll
        for (int o = 1; o < 32; o <<= 1) {
            int y = __shfl_up_sync(0xffffffffu, s, o);
            if (lane >= o) s += y;
        }
        swarp[lane] = s;
    }
    __syncthreads();
    int incl = x + (w > 0 ? swarp[w - 1] : 0);
    if (i < NN) g_rowptr[i + 1] = incl;
    if (tid == 1023) g_bsum[blockIdx.x] = incl;
}

__global__ void scan2_kernel() {
    if (threadIdx.x == 0) {
        int acc = 0;
        for (int b = 0; b < NSCAN_BLK; b++) {
            int v = g_bsum[b];
            g_bsum[b] = acc;
            acc += v;
        }
    }
}

__global__ void scan3_kernel() {
    int i = blockIdx.x * 1024 + threadIdx.x;
    if (i < NN) {
        int val = g_rowptr[i + 1] + g_bsum[blockIdx.x];
        g_rowptr[i + 1] = val;
        g_cursor[i] = val - g_deg[i];
        if (i == 0) g_rowptr[0] = 0;
    }
}

__global__ void scatter_kernel(const int* __restrict__ ei) {
    int e = blockIdx.x * blockDim.x + threadIdx.x;
    if (e < EE) {
        int d = ei[EE + e];
        int p = atomicAdd(&g_cursor[d], 1);
        g_colidx[p] = ei[e];
    }
}

__global__ void gscan_kernel() {
    if (threadIdx.x == 0) {
        int acc = 0;
        for (int g = 0; g < GG; g++) {
            g_gstart[g] = acc;
            int c = g_gc[g];
            acc += c;
            g_invcnt[g] = 1.0f / (float)(c > 1 ? c : 1);
        }
        g_gstart[GG] = acc;
    }
}

// ---------------- weight transpose + split: W[k][n] -> Wt[n][k] bf16 hi/lo --
__global__ void wsplit_kernel(const float* __restrict__ W1,
                              const float* __restrict__ W2) {
    __shared__ float tile[32][33];
    int mat = blockIdx.z;   // 0..7 : layer = mat>>1, (mat&1)? W2 : W1
    const float* W = ((mat & 1) ? W2 : W1) + (size_t)(mat >> 1) * DD * DD;
    int k0 = blockIdx.x * 32, n0 = blockIdx.y * 32;
    int tx = threadIdx.x, ty = threadIdx.y;
    tile[ty][tx] = W[(size_t)(k0 + ty) * DD + n0 + tx];
    __syncthreads();
    float v = tile[tx][ty];          // = W[k0+tx][n0+ty]
    __nv_bfloat16 h = __float2bfloat16_rn(v);
    __nv_bfloat16 l = __float2bfloat16_rn(v - __bfloat162float(h));
    size_t o = (size_t)mat * DD * DD + (size_t)(n0 + ty) * DD + k0 + tx;
    g_whi[o] = h;
    g_wlo[o] = l;
}

// zero the 48 pad rows of split activation arrays
__global__ void padzero_kernel() {
    int i = blockIdx.x * 256 + threadIdx.x;
    if (i < (NP - NN) * DD) {
        size_t idx = (size_t)NN * DD + i;
        __nv_bfloat16 z = __float2bfloat16_rn(0.f);
        g_ahi[idx] = z; g_alo[idx] = z; g_thi[idx] = z; g_tlo[idx] = z;
    }
}

// ------- GIN aggregation: h[n] = z[n] + sum_{src->n} z[src]; writes split ---
__global__ void agg_kernel(const float* __restrict__ xin) {
    const float* __restrict__ zin = xin ? xin : g_z;
    int n = blockIdx.x;
    int t = threadIdx.x;               // 128 threads, one float4 each
    const float4* Z = (const float4*)zin;
    float4 acc = Z[(size_t)n * 128 + t];
    int e = g_rowptr[n], end = g_rowptr[n + 1];
    for (; e + 4 <= end; e += 4) {
        int s0 = g_colidx[e], s1 = g_colidx[e + 1], s2 = g_colidx[e + 2], s3 = g_colidx[e + 3];
        float4 v0 = Z[(size_t)s0 * 128 + t];
        float4 v1 = Z[(size_t)s1 * 128 + t];
        float4 v2 = Z[(size_t)s2 * 128 + t];
        float4 v3 = Z[(size_t)s3 * 128 + t];
        acc.x += v0.x + v1.x + v2.x + v3.x;
        acc.y += v0.y + v1.y + v2.y + v3.y;
        acc.z += v0.z + v1.z + v2.z + v3.z;
        acc.w += v0.w + v1.w + v2.w + v3.w;
    }
    for (; e < end; e++) {
        float4 v = Z[(size_t)g_colidx[e] * 128 + t];
        acc.x += v.x; acc.y += v.y; acc.z += v.z; acc.w += v.w;
    }
    uint32_t h0, l0, h1, l1;
    split2(acc.x, acc.y, h0, l0);
    split2(acc.z, acc.w, h1, l1);
    ((uint2*)g_ahi)[(size_t)n * 128 + t] = make_uint2(h0, h1);
    ((uint2*)g_alo)[(size_t)n * 128 + t] = make_uint2(l0, l1);
}

// ------------- GEMM: C = relu(A @ W + bias), 3xBF16, cp.async pipeline ------
// A: [NP][512] bf16 hi/lo row-major. B: W^T [n][k] bf16 hi/lo.
// Block tile 128x128, K-tile 32 (2 k16 steps), 256 threads, warp tile 32x64.
// smem per stage (uint32): aHi 128*20, aLo, bHi, bLo -> 10240 u32 = 40KB; 2 stages.
#define SROW 20                // uint32 per row: 16 k-pairs + 4 pad (16B-aligned)
#define STAGE_U32 (4 * 128 * SROW)
#define GEMM_SMEM_BYTES (2 * STAGE_U32 * 4)

__global__ __launch_bounds__(256, 2) void gemm_bf16_kernel(
    int mode,            // 0: A=g_ahi/alo, out split -> g_thi/tlo ; 1: A=g_thi/tlo, out fp32 -> g_h
    int woff,            // offset into g_whi/g_wlo (elements)
    const float* __restrict__ bias)
{
    extern __shared__ uint32_t smem[];
    const __nv_bfloat16* __restrict__ Ahi = mode ? g_thi : g_ahi;
    const __nv_bfloat16* __restrict__ Alo = mode ? g_tlo : g_alo;
    const __nv_bfloat16* __restrict__ Bhi = g_whi + woff;
    const __nv_bfloat16* __restrict__ Blo = g_wlo + woff;

    int tid  = threadIdx.x;
    int lane = tid & 31;
    int warp = tid >> 5;
    int wm = warp >> 1;          // 0..3
    int wn = warp & 1;           // 0..1
    int m0 = blockIdx.x * 128;
    int n0 = blockIdx.y * 128;

    float acc[2][8][4];
#pragma unroll
    for (int mi = 0; mi < 2; mi++)
#pragma unroll
        for (int ni = 0; ni < 8; ni++)
#pragma unroll
            for (int j = 0; j < 4; j++) acc[mi][ni][j] = 0.f;

    uint32_t sbase = (uint32_t)__cvta_generic_to_shared(smem);

    auto prefetch = [&](int kt, int s) {
        int k0 = kt * 32;
        uint32_t b = sbase + (uint32_t)s * STAGE_U32 * 4;
#pragma unroll
        for (int c = 0; c < 2; c++) {
            int id = tid + c * 256;          // 0..511
            int row = id >> 2;               // 0..127
            int cc = id & 3;                 // 16B chunk within row
            uint32_t doff = (uint32_t)(row * SROW + cc * 4) * 4u;
            size_t go = (size_t)row * DD + k0 + cc * 8;
            cp_async16(b + doff,                          Ahi + (size_t)m0 * DD + go);
            cp_async16(b + 128 * SROW * 4 + doff,         Alo + (size_t)m0 * DD + go);
            cp_async16(b + 2 * 128 * SROW * 4 + doff,     Bhi + (size_t)n0 * DD + go);
            cp_async16(b + 3 * 128 * SROW * 4 + doff,     Blo + (size_t)n0 * DD + go);
        }
        asm volatile("cp.async.commit_group;\n" ::);
    };

    prefetch(0, 0);

    for (int kt = 0; kt < 16; kt++) {
        if (kt < 15) {
            prefetch(kt + 1, (kt + 1) & 1);
            asm volatile("cp.async.wait_group 1;\n" ::);
        } else {
            asm volatile("cp.async.wait_group 0;\n" ::);
        }
        __syncthreads();

        uint32_t* buf   = smem + (kt & 1) * STAGE_U32;
        uint32_t* sa_hi = buf;
        uint32_t* sa_lo = buf + 128 * SROW;
        uint32_t* sb_hi = buf + 2 * 128 * SROW;
        uint32_t* sb_lo = buf + 3 * 128 * SROW;

#pragma unroll
        for (int kk = 0; kk < 2; kk++) {
            uint32_t afh[2][4], afl[2][4], bfh[8][2], bfl[8][2];
            int ar = wm * 32 + (lane >> 2);
            int ac = kk * 8 + (lane & 3);
#pragma unroll
            for (int mi = 0; mi < 2; mi++) {
                int r0 = ar + mi * 16;
                int i00 = r0 * SROW + ac;
                int i10 = (r0 + 8) * SROW + ac;
                afh[mi][0] = sa_hi[i00];     afh[mi][1] = sa_hi[i10];
                afh[mi][2] = sa_hi[i00 + 4]; afh[mi][3] = sa_hi[i10 + 4];
                afl[mi][0] = sa_lo[i00];     afl[mi][1] = sa_lo[i10];
                afl[mi][2] = sa_lo[i00 + 4]; afl[mi][3] = sa_lo[i10 + 4];
            }
            int bk = kk * 8 + (lane & 3);
            int bc = wn * 64 + (lane >> 2);
#pragma unroll
            for (int ni = 0; ni < 8; ni++) {
                int nidx = (bc + ni * 8) * SROW;
                bfh[ni][0] = sb_hi[nidx + bk]; bfh[ni][1] = sb_hi[nidx + bk + 4];
                bfl[ni][0] = sb_lo[nidx + bk]; bfl[ni][1] = sb_lo[nidx + bk + 4];
            }
#pragma unroll
            for (int mi = 0; mi < 2; mi++)
#pragma unroll
                for (int ni = 0; ni < 8; ni++) {
                    mma_bf16(acc[mi][ni], afl[mi], bfh[ni]);   // a_lo * b_hi
                    mma_bf16(acc[mi][ni], afh[mi], bfl[ni]);   // a_hi * b_lo
                    mma_bf16(acc[mi][ni], afh[mi], bfh[ni]);   // a_hi * b_hi
                }
        }
        __syncthreads();
    }

    // epilogue: relu(acc + bias)
    int rbase = m0 + wm * 32 + (lane >> 2);
    int cbase = n0 + wn * 64 + (lane & 3) * 2;
#pragma unroll
    for (int mi = 0; mi < 2; mi++) {
#pragma unroll
        for (int ni = 0; ni < 8; ni++) {
            int c = cbase + ni * 8;
            float b0 = __ldg(&bias[c]);
            float b1 = __ldg(&bias[c + 1]);
#pragma unroll
            for (int half = 0; half < 2; half++) {
                int r = rbase + mi * 16 + half * 8;
                if (r < NN) {
                    float vx = fmaxf(acc[mi][ni][half * 2 + 0] + b0, 0.f);
                    float vy = fmaxf(acc[mi][ni][half * 2 + 1] + b1, 0.f);
                    if (mode == 0) {
                        uint32_t h, l;
                        split2(vx, vy, h, l);
                        *(uint32_t*)(g_thi + (size_t)r * DD + c) = h;
                        *(uint32_t*)(g_tlo + (size_t)r * DD + c) = l;
                    } else {
                        float2 v; v.x = vx; v.y = vy;
                        *(float2*)(g_h + (size_t)r * DD + c) = v;
                    }
                }
            }
        }
    }
}

// ---------------- BatchNorm stats + normalize + pool ------------------------
__global__ void zero_stats_kernel() {
    int c = threadIdx.x;
    if (c < DD) { g_sum[c] = 0.f; g_sq[c] = 0.f; }
}

__global__ void bn_stats_kernel() {   // grid (4, 256), block 128
    int col = blockIdx.x * 128 + threadIdx.x;
    float s = 0.f, q = 0.f;
    for (int r = blockIdx.y; r < NN; r += gridDim.y) {
        float v = g_h[(size_t)r * DD + col];
        s += v;
        q += v * v;
    }
    atomicAdd(&g_sum[col], s);
    atomicAdd(&g_sq[col], q);
}

__global__ void bn_finalize_kernel() {
    int c = threadIdx.x;
    if (c < DD) {
        float mu  = g_sum[c] * (1.0f / NN);
        float var = g_sq[c] * (1.0f / NN) - mu * mu;
        g_mu[c]   = mu;
        g_rstd[c] = rsqrtf(fmaxf(var, 0.f) + 1e-5f);
    }
}

__global__ void bn_pool_kernel(float* __restrict__ out, int layer,
                               const float* __restrict__ gamma,
                               const float* __restrict__ beta)
{
    int g   = blockIdx.x;
    int col = blockIdx.y * 128 + threadIdx.x;
    int s = g_gstart[g], e = g_gstart[g + 1];
    float a = g_rstd[col] * __ldg(&gamma[col]);
    float b = __ldg(&beta[col]) - g_mu[col] * a;
    float acc = 0.f;
    for (int r = s; r < e; r++) {
        float v  = g_h[(size_t)r * DD + col];
        float vn = v * a + b;
        g_z[(size_t)r * DD + col] = vn;
        acc += vn;
    }
    out[g * (LL * DD) + layer * DD + col] = acc * g_invcnt[g];
}

// ---------------- launcher --------------------------------------------------
extern "C" void kernel_launch(void* const* d_in, const int* in_sizes, int n_in,
                              void* d_out, int out_size)
{
    const float* x     = (const float*)d_in[0];
    const float* W1    = (const float*)d_in[1];
    const float* b1    = (const float*)d_in[2];
    const float* W2    = (const float*)d_in[3];
    const float* b2    = (const float*)d_in[4];
    const float* gamma = (const float*)d_in[5];
    const float* beta  = (const float*)d_in[6];
    const int*   ei    = (const int*)d_in[7];     // int32 (JAX x64 disabled)
    const int*   batch = (const int*)d_in[8];     // int32
    float* out = (float*)d_out;

    cudaFuncSetAttribute(gemm_bf16_kernel,
                         cudaFuncAttributeMaxDynamicSharedMemorySize,
                         GEMM_SMEM_BYTES);

    // one-time per call: weight transpose+split, pad-zero, CSR build
    wsplit_kernel<<<dim3(16, 16, 8), dim3(32, 32)>>>(W1, W2);
    padzero_kernel<<<((NP - NN) * DD + 255) / 256, 256>>>();
    zero_csr_kernel<<<196, 256>>>();
    edge_hist_kernel<<<(EE + 255) / 256, 256>>>(ei);
    node_hist_kernel<<<(NN + 255) / 256, 256>>>(batch);
    scan1_kernel<<<NSCAN_BLK, 1024>>>();
    scan2_kernel<<<1, 32>>>();
    scan3_kernel<<<NSCAN_BLK, 1024>>>();
    scatter_kernel<<<(EE + 255) / 256, 256>>>(ei);
    gscan_kernel<<<1, 32>>>();

    dim3 ggrid(NP / 128, 4);
    for (int i = 0; i < LL; i++) {
        agg_kernel<<<NN, 128>>>(i == 0 ? x : nullptr);
        gemm_bf16_kernel<<<ggrid, 256, GEMM_SMEM_BYTES>>>(
            0, (2 * i) * DD * DD, b1 + i * DD);
        gemm_bf16_kernel<<<ggrid, 256, GEMM_SMEM_BYTES>>>(
            1, (2 * i + 1) * DD * DD, b2 + i * DD);
        zero_stats_kernel<<<1, 512>>>();
        bn_stats_kernel<<<dim3(4, 256), 128>>>();
        bn_finalize_kernel<<<1, 512>>>();
        bn_pool_kernel<<<dim3(GG, 4), 128>>>(out, i, gamma, beta);
    }
}

// round 8
// speedup vs baseline: 1.7864x; 1.1843x over previous
#include <cuda_runtime.h>
#include <cuda_bf16.h>
#include <cstdint>
#include <cstddef>

#define NN 50000
#define NP 50048           // padded rows (multiple of 128)
#define EE 400000
#define DD 512
#define GG 128
#define LL 4
#define NSCAN_BLK 49       // ceil(50000/1024)

// ---------------- scratch (static device allocations; no cudaMalloc) -------
__device__ float g_h[(size_t)NN * DD];            // gemm2 output (pre-BN), fp32
__device__ __nv_bfloat16 g_ahi[(size_t)NP * DD];  // agg output, split hi
__device__ __nv_bfloat16 g_alo[(size_t)NP * DD];  // agg output, split lo
__device__ __nv_bfloat16 g_thi[(size_t)NP * DD];  // gemm1 output, split hi
__device__ __nv_bfloat16 g_tlo[(size_t)NP * DD];  // gemm1 output, split lo
__device__ __nv_bfloat16 g_whi[(size_t)8 * DD * DD];  // W^T split hi, [mat][n][k]
__device__ __nv_bfloat16 g_wlo[(size_t)8 * DD * DD];  // W^T split lo
__device__ int   g_deg[NN];
__device__ int   g_rowptr[NN + 1];
__device__ int   g_cursor[NN];
__device__ int   g_colidx[EE];
__device__ int   g_bsum[NSCAN_BLK];
__device__ int   g_gc[GG];
__device__ int   g_gstart[GG + 1];
__device__ float g_invcnt[GG];
__device__ float g_sum[DD];
__device__ float g_sq[DD];
__device__ float g_mu[DD];
__device__ float g_rstd[DD];

// ---------------- helpers ---------------------------------------------------
__device__ __forceinline__ void split2(float x, float y, uint32_t& hi, uint32_t& lo) {
    __nv_bfloat162 h = __floats2bfloat162_rn(x, y);   // .x in low 16 bits
    float hx = __bfloat162float(h.x);
    float hy = __bfloat162float(h.y);
    __nv_bfloat162 l = __floats2bfloat162_rn(x - hx, y - hy);
    hi = *(uint32_t*)&h;
    lo = *(uint32_t*)&l;
}

__device__ __forceinline__ void mma_bf16(float* c, const uint32_t* a, const uint32_t* b) {
    asm volatile(
        "mma.sync.aligned.m16n8k16.row.col.f32.bf16.bf16.f32 "
        "{%0,%1,%2,%3}, {%4,%5,%6,%7}, {%8,%9}, {%0,%1,%2,%3};\n"
        : "+f"(c[0]), "+f"(c[1]), "+f"(c[2]), "+f"(c[3])
        : "r"(a[0]), "r"(a[1]), "r"(a[2]), "r"(a[3]), "r"(b[0]), "r"(b[1]));
}

__device__ __forceinline__ void cp_async16(uint32_t saddr, const void* gaddr) {
    asm volatile("cp.async.cg.shared.global [%0], [%1], 16;\n"
                 :: "r"(saddr), "l"(gaddr));
}

// ---------------- CSR build -------------------------------------------------
__global__ void zero_csr_kernel() {
    int i = blockIdx.x * blockDim.x + threadIdx.x;
    int stride = gridDim.x * blockDim.x;
    for (int j = i; j < NN; j += stride) g_deg[j] = 0;
    if (i < GG) g_gc[i] = 0;
    if (i < DD) { g_sum[i] = 0.f; g_sq[i] = 0.f; }
}

__global__ void edge_hist_kernel(const int* __restrict__ ei) {
    int e = blockIdx.x * blockDim.x + threadIdx.x;
    if (e < EE) atomicAdd(&g_deg[ei[EE + e]], 1);
}

__global__ void node_hist_kernel(const int* __restrict__ batch) {
    int i = blockIdx.x * blockDim.x + threadIdx.x;
    if (i < NN) atomicAdd(&g_gc[batch[i]], 1);
}

__global__ void scan1_kernel() {
    __shared__ int swarp[32];
    int tid = threadIdx.x;
    int i = blockIdx.x * 1024 + tid;
    int lane = tid & 31, w = tid >> 5;
    int v = (i < NN) ? g_deg[i] : 0;
    int x = v;
#pragma unroll
    for (int o = 1; o < 32; o <<= 1) {
        int y = __shfl_up_sync(0xffffffffu, x, o);
        if (lane >= o) x += y;
    }
    if (lane == 31) swarp[w] = x;
    __syncthreads();
    if (w == 0) {
        int s = swarp[lane];
#pragma unroll
        for (int o = 1; o < 32; o <<= 1) {
            int y = __shfl_up_sync(0xffffffffu, s, o);
            if (lane >= o) s += y;
        }
        swarp[lane] = s;
    }
    __syncthreads();
    int incl = x + (w > 0 ? swarp[w - 1] : 0);
    if (i < NN) g_rowptr[i + 1] = incl;
    if (tid == 1023) g_bsum[blockIdx.x] = incl;
}

__global__ void scan2_kernel() {
    if (threadIdx.x == 0) {
        int acc = 0;
        for (int b = 0; b < NSCAN_BLK; b++) {
            int v = g_bsum[b];
            g_bsum[b] = acc;
            acc += v;
        }
    }
}

__global__ void scan3_kernel() {
    int i = blockIdx.x * 1024 + threadIdx.x;
    if (i < NN) {
        int val = g_rowptr[i + 1] + g_bsum[blockIdx.x];
        g_rowptr[i + 1] = val;
        g_cursor[i] = val - g_deg[i];
        if (i == 0) g_rowptr[0] = 0;
    }
}

__global__ void scatter_kernel(const int* __restrict__ ei) {
    int e = blockIdx.x * blockDim.x + threadIdx.x;
    if (e < EE) {
        int d = ei[EE + e];
        int p = atomicAdd(&g_cursor[d], 1);
        g_colidx[p] = ei[e];
    }
}

__global__ void gscan_kernel() {
    if (threadIdx.x == 0) {
        int acc = 0;
        for (int g = 0; g < GG; g++) {
            g_gstart[g] = acc;
            int c = g_gc[g];
            acc += c;
            g_invcnt[g] = 1.0f / (float)(c > 1 ? c : 1);
        }
        g_gstart[GG] = acc;
    }
}

// ---------------- weight transpose + split: W[k][n] -> Wt[n][k] bf16 hi/lo --
__global__ void wsplit_kernel(const float* __restrict__ W1,
                              const float* __restrict__ W2) {
    __shared__ float tile[32][33];
    int mat = blockIdx.z;   // 0..7 : layer = mat>>1, (mat&1)? W2 : W1
    const float* W = ((mat & 1) ? W2 : W1) + (size_t)(mat >> 1) * DD * DD;
    int k0 = blockIdx.x * 32, n0 = blockIdx.y * 32;
    int tx = threadIdx.x, ty = threadIdx.y;
    tile[ty][tx] = W[(size_t)(k0 + ty) * DD + n0 + tx];
    __syncthreads();
    float v = tile[tx][ty];          // = W[k0+tx][n0+ty]
    __nv_bfloat16 h = __float2bfloat16_rn(v);
    __nv_bfloat16 l = __float2bfloat16_rn(v - __bfloat162float(h));
    size_t o = (size_t)mat * DD * DD + (size_t)(n0 + ty) * DD + k0 + tx;
    g_whi[o] = h;
    g_wlo[o] = l;
}

__global__ void padzero_kernel() {
    int i = blockIdx.x * 256 + threadIdx.x;
    if (i < (NP - NN) * DD) {
        size_t idx = (size_t)NN * DD + i;
        __nv_bfloat16 z = __float2bfloat16_rn(0.f);
        g_ahi[idx] = z; g_alo[idx] = z; g_thi[idx] = z; g_tlo[idx] = z;
    }
}

// ------- GIN aggregation with fused BN affine -------------------------------
// layer 0 (xin != null): agg = x_n + sum x_src, no affine.
// layer >0: raw = h_n + sum h_src (pre-BN h), then z-agg = raw*a + (deg+1)*b
// where a = rstd*gamma, b = beta - mu*a (BN affine commutes with summation).
__global__ void agg_kernel(const float* __restrict__ xin,
                           const float* __restrict__ gamma,
                           const float* __restrict__ beta) {
    const float* __restrict__ zin = xin ? xin : g_h;
    int n = blockIdx.x;
    int t = threadIdx.x;               // 128 threads, one float4 each
    const float4* Z = (const float4*)zin;
    float4 acc = Z[(size_t)n * 128 + t];
    int e = g_rowptr[n], end = g_rowptr[n + 1];
    int deg = end - e;
    for (; e + 4 <= end; e += 4) {
        int s0 = g_colidx[e], s1 = g_colidx[e + 1], s2 = g_colidx[e + 2], s3 = g_colidx[e + 3];
        float4 v0 = Z[(size_t)s0 * 128 + t];
        float4 v1 = Z[(size_t)s1 * 128 + t];
        float4 v2 = Z[(size_t)s2 * 128 + t];
        float4 v3 = Z[(size_t)s3 * 128 + t];
        acc.x += v0.x + v1.x + v2.x + v3.x;
        acc.y += v0.y + v1.y + v2.y + v3.y;
        acc.z += v0.z + v1.z + v2.z + v3.z;
        acc.w += v0.w + v1.w + v2.w + v3.w;
    }
    for (; e < end; e++) {
        float4 v = Z[(size_t)g_colidx[e] * 128 + t];
        acc.x += v.x; acc.y += v.y; acc.z += v.z; acc.w += v.w;
    }
    if (!xin) {
        int c = t * 4;
        float4 mu = *(const float4*)&g_mu[c];
        float4 rs = *(const float4*)&g_rstd[c];
        float4 ga = *(const float4*)&gamma[c];
        float4 be = *(const float4*)&beta[c];
        float k = (float)(deg + 1);
        float a0 = rs.x * ga.x, b0 = be.x - mu.x * a0;
        float a1 = rs.y * ga.y, b1 = be.y - mu.y * a1;
        float a2 = rs.z * ga.z, b2 = be.z - mu.z * a2;
        float a3 = rs.w * ga.w, b3 = be.w - mu.w * a3;
        acc.x = acc.x * a0 + b0 * k;
        acc.y = acc.y * a1 + b1 * k;
        acc.z = acc.z * a2 + b2 * k;
        acc.w = acc.w * a3 + b3 * k;
    }
    uint32_t h0, l0, h1, l1;
    split2(acc.x, acc.y, h0, l0);
    split2(acc.z, acc.w, h1, l1);
    ((uint2*)g_ahi)[(size_t)n * 128 + t] = make_uint2(h0, h1);
    ((uint2*)g_alo)[(size_t)n * 128 + t] = make_uint2(l0, l1);
}

// ------------- GEMM: C = relu(A @ W + bias), 3xBF16, cp.async pipeline ------
// mode 1 epilogue additionally accumulates per-column sum / sumsq into
// g_sum / g_sq (BN statistics fused into the GEMM).
#define SROW 20                // uint32 per row: 16 k-pairs + 4 pad (16B-aligned)
#define STAGE_U32 (4 * 128 * SROW)
#define GEMM_SMEM_BYTES (2 * STAGE_U32 * 4)

__global__ __launch_bounds__(256, 2) void gemm_bf16_kernel(
    int mode,            // 0: A=g_ahi/alo, out split -> g_thi/tlo ; 1: A=g_thi/tlo, out fp32 -> g_h (+stats)
    int woff,            // offset into g_whi/g_wlo (elements)
    const float* __restrict__ bias)
{
    extern __shared__ uint32_t smem[];
    __shared__ float ssum[128];
    __shared__ float ssq[128];
    const __nv_bfloat16* __restrict__ Ahi = mode ? g_thi : g_ahi;
    const __nv_bfloat16* __restrict__ Alo = mode ? g_tlo : g_alo;
    const __nv_bfloat16* __restrict__ Bhi = g_whi + woff;
    const __nv_bfloat16* __restrict__ Blo = g_wlo + woff;

    int tid  = threadIdx.x;
    int lane = tid & 31;
    int warp = tid >> 5;
    int wm = warp >> 1;          // 0..3
    int wn = warp & 1;           // 0..1
    int m0 = blockIdx.x * 128;
    int n0 = blockIdx.y * 128;

    if (tid < 128) { ssum[tid] = 0.f; ssq[tid] = 0.f; }

    float acc[2][8][4];
#pragma unroll
    for (int mi = 0; mi < 2; mi++)
#pragma unroll
        for (int ni = 0; ni < 8; ni++)
#pragma unroll
            for (int j = 0; j < 4; j++) acc[mi][ni][j] = 0.f;

    uint32_t sbase = (uint32_t)__cvta_generic_to_shared(smem);

    auto prefetch = [&](int kt, int s) {
        int k0 = kt * 32;
        uint32_t b = sbase + (uint32_t)s * STAGE_U32 * 4;
#pragma unroll
        for (int c = 0; c < 2; c++) {
            int id = tid + c * 256;          // 0..511
            int row = id >> 2;               // 0..127
            int cc = id & 3;                 // 16B chunk within row
            uint32_t doff = (uint32_t)(row * SROW + cc * 4) * 4u;
            size_t go = (size_t)row * DD + k0 + cc * 8;
            cp_async16(b + doff,                          Ahi + (size_t)m0 * DD + go);
            cp_async16(b + 128 * SROW * 4 + doff,         Alo + (size_t)m0 * DD + go);
            cp_async16(b + 2 * 128 * SROW * 4 + doff,     Bhi + (size_t)n0 * DD + go);
            cp_async16(b + 3 * 128 * SROW * 4 + doff,     Blo + (size_t)n0 * DD + go);
        }
        asm volatile("cp.async.commit_group;\n" ::);
    };

    prefetch(0, 0);

    for (int kt = 0; kt < 16; kt++) {
        if (kt < 15) {
            prefetch(kt + 1, (kt + 1) & 1);
            asm volatile("cp.async.wait_group 1;\n" ::);
        } else {
            asm volatile("cp.async.wait_group 0;\n" ::);
        }
        __syncthreads();

        uint32_t* buf   = smem + (kt & 1) * STAGE_U32;
        uint32_t* sa_hi = buf;
        uint32_t* sa_lo = buf + 128 * SROW;
        uint32_t* sb_hi = buf + 2 * 128 * SROW;
        uint32_t* sb_lo = buf + 3 * 128 * SROW;

#pragma unroll
        for (int kk = 0; kk < 2; kk++) {
            uint32_t afh[2][4], afl[2][4], bfh[8][2], bfl[8][2];
            int ar = wm * 32 + (lane >> 2);
            int ac = kk * 8 + (lane & 3);
#pragma unroll
            for (int mi = 0; mi < 2; mi++) {
                int r0 = ar + mi * 16;
                int i00 = r0 * SROW + ac;
                int i10 = (r0 + 8) * SROW + ac;
                afh[mi][0] = sa_hi[i00];     afh[mi][1] = sa_hi[i10];
                afh[mi][2] = sa_hi[i00 + 4]; afh[mi][3] = sa_hi[i10 + 4];
                afl[mi][0] = sa_lo[i00];     afl[mi][1] = sa_lo[i10];
                afl[mi][2] = sa_lo[i00 + 4]; afl[mi][3] = sa_lo[i10 + 4];
            }
            int bk = kk * 8 + (lane & 3);
            int bc = wn * 64 + (lane >> 2);
#pragma unroll
            for (int ni = 0; ni < 8; ni++) {
                int nidx = (bc + ni * 8) * SROW;
                bfh[ni][0] = sb_hi[nidx + bk]; bfh[ni][1] = sb_hi[nidx + bk + 4];
                bfl[ni][0] = sb_lo[nidx + bk]; bfl[ni][1] = sb_lo[nidx + bk + 4];
            }
#pragma unroll
            for (int mi = 0; mi < 2; mi++)
#pragma unroll
                for (int ni = 0; ni < 8; ni++) {
                    mma_bf16(acc[mi][ni], afl[mi], bfh[ni]);   // a_lo * b_hi
                    mma_bf16(acc[mi][ni], afh[mi], bfl[ni]);   // a_hi * b_lo
                    mma_bf16(acc[mi][ni], afh[mi], bfh[ni]);   // a_hi * b_hi
                }
        }
        __syncthreads();
    }

    // epilogue: relu(acc + bias) (+ fused BN stats in mode 1)
    int rbase = m0 + wm * 32 + (lane >> 2);
    int cbase = n0 + wn * 64 + (lane & 3) * 2;
#pragma unroll
    for (int ni = 0; ni < 8; ni++) {
        int c = cbase + ni * 8;
        float b0 = __ldg(&bias[c]);
        float b1 = __ldg(&bias[c + 1]);
        float sx = 0.f, sy = 0.f, qx = 0.f, qy = 0.f;
#pragma unroll
        for (int mi = 0; mi < 2; mi++) {
#pragma unroll
            for (int half = 0; half < 2; half++) {
                int r = rbase + mi * 16 + half * 8;
                if (r < NN) {
                    float vx = fmaxf(acc[mi][ni][half * 2 + 0] + b0, 0.f);
                    float vy = fmaxf(acc[mi][ni][half * 2 + 1] + b1, 0.f);
                    if (mode == 0) {
                        uint32_t h, l;
                        split2(vx, vy, h, l);
                        *(uint32_t*)(g_thi + (size_t)r * DD + c) = h;
                        *(uint32_t*)(g_tlo + (size_t)r * DD + c) = l;
                    } else {
                        float2 v; v.x = vx; v.y = vy;
                        *(float2*)(g_h + (size_t)r * DD + c) = v;
                        sx += vx; sy += vy;
                        qx += vx * vx; qy += vy * vy;
                    }
                }
            }
        }
        if (mode == 1) {
            int crel = c - n0;
            atomicAdd(&ssum[crel], sx);
            atomicAdd(&ssum[crel + 1], sy);
            atomicAdd(&ssq[crel], qx);
            atomicAdd(&ssq[crel + 1], qy);
        }
    }
    if (mode == 1) {
        __syncthreads();
        if (tid < 128) {
            atomicAdd(&g_sum[n0 + tid], ssum[tid]);
            atomicAdd(&g_sq[n0 + tid], ssq[tid]);
        }
    }
}

// ---------------- BN finalize (self-zeroing) + pool -------------------------
__global__ void bn_finalize_kernel() {
    int c = threadIdx.x;
    if (c < DD) {
        float s = g_sum[c], q = g_sq[c];
        float mu  = s * (1.0f / NN);
        float var = q * (1.0f / NN) - mu * mu;
        g_mu[c]   = mu;
        g_rstd[c] = rsqrtf(fmaxf(var, 0.f) + 1e-5f);
        g_sum[c] = 0.f;           // ready for next layer's fused stats
        g_sq[c]  = 0.f;
    }
}

// pool raw h per graph, apply BN affine to the mean: (sum*a)*inv + b
__global__ void bn_pool_kernel(float* __restrict__ out, int layer,
                               const float* __restrict__ gamma,
                               const float* __restrict__ beta)
{
    int g   = blockIdx.x;
    int col = blockIdx.y * 128 + threadIdx.x;
    int s = g_gstart[g], e = g_gstart[g + 1];
    float a = g_rstd[col] * __ldg(&gamma[col]);
    float b = __ldg(&beta[col]) - g_mu[col] * a;
    float acc = 0.f;
    for (int r = s; r < e; r++)
        acc += g_h[(size_t)r * DD + col];
    float res = (e > s) ? acc * a * g_invcnt[g] + b : 0.f;
    out[g * (LL * DD) + layer * DD + col] = res;
}

// ---------------- launcher --------------------------------------------------
extern "C" void kernel_launch(void* const* d_in, const int* in_sizes, int n_in,
                              void* d_out, int out_size)
{
    const float* x     = (const float*)d_in[0];
    const float* W1    = (const float*)d_in[1];
    const float* b1    = (const float*)d_in[2];
    const float* W2    = (const float*)d_in[3];
    const float* b2    = (const float*)d_in[4];
    const float* gamma = (const float*)d_in[5];
    const float* beta  = (const float*)d_in[6];
    const int*   ei    = (const int*)d_in[7];     // int32 (JAX x64 disabled)
    const int*   batch = (const int*)d_in[8];     // int32
    float* out = (float*)d_out;

    cudaFuncSetAttribute(gemm_bf16_kernel,
                         cudaFuncAttributeMaxDynamicSharedMemorySize,
                         GEMM_SMEM_BYTES);

    wsplit_kernel<<<dim3(16, 16, 8), dim3(32, 32)>>>(W1, W2);
    padzero_kernel<<<((NP - NN) * DD + 255) / 256, 256>>>();
    zero_csr_kernel<<<196, 256>>>();
    edge_hist_kernel<<<(EE + 255) / 256, 256>>>(ei);
    node_hist_kernel<<<(NN + 255) / 256, 256>>>(batch);
    scan1_kernel<<<NSCAN_BLK, 1024>>>();
    scan2_kernel<<<1, 32>>>();
    scan3_kernel<<<NSCAN_BLK, 1024>>>();
    scatter_kernel<<<(EE + 255) / 256, 256>>>(ei);
    gscan_kernel<<<1, 32>>>();

    dim3 ggrid(NP / 128, 4);
    for (int i = 0; i < LL; i++) {
        agg_kernel<<<NN, 128>>>(i == 0 ? x : nullptr, gamma, beta);
        gemm_bf16_kernel<<<ggrid, 256, GEMM_SMEM_BYTES>>>(
            0, (2 * i) * DD * DD, b1 + i * DD);
        gemm_bf16_kernel<<<ggrid, 256, GEMM_SMEM_BYTES>>>(
            1, (2 * i + 1) * DD * DD, b2 + i * DD);
        bn_finalize_kernel<<<1, 512>>>();
        bn_pool_kernel<<<dim3(GG, 4), 128>>>(out, i, gamma, beta);
    }
}